// round 2
// baseline (speedup 1.0000x reference)
#include <cuda_runtime.h>
#include <cuda_bf16.h>

#define HIDDEN 2048
#define INTER  1408
#define TOP_K  4

// Scratch for weighted intermediate activations: topk_w[e] * silu(gate)*up
__device__ float g_inter[TOP_K * INTER];

// ---------------------------------------------------------------------------
// Kernel 1: for each selected expert e and each intermediate row i:
//   g = dot(gate[ex][i][:], x);  u = dot(up[ex][i][:], x);
//   g_inter[e][i] = topk_w[e] * silu(g) * u
// grid: (INTER/8 = 176, TOP_K), block: 256 threads (8 warps, 1 row per warp)
// ---------------------------------------------------------------------------
__global__ __launch_bounds__(256)
void moe_gate_up_kernel(const float* __restrict__ x,
                        const int*   __restrict__ topk_idx,
                        const float* __restrict__ topk_w,
                        const float* __restrict__ gate_all,
                        const float* __restrict__ up_all)
{
    __shared__ float4 x_s[HIDDEN / 4];   // 8 KB

    const int tid  = threadIdx.x;
    const int lane = tid & 31;
    const int warp = tid >> 5;

    // Stage x into shared memory: 512 float4 / 256 threads = 2 each
    const float4* x4 = reinterpret_cast<const float4*>(x);
    x_s[tid]       = x4[tid];
    x_s[tid + 256] = x4[tid + 256];
    __syncthreads();

    const int e   = blockIdx.y;                 // expert slot 0..3
    const int row = blockIdx.x * 8 + warp;      // 0..1407
    const long long ex = topk_idx[e];

    const float4* g4 = reinterpret_cast<const float4*>(
        gate_all + (ex * INTER + row) * (long long)HIDDEN);
    const float4* u4 = reinterpret_cast<const float4*>(
        up_all   + (ex * INTER + row) * (long long)HIDDEN);

    float gacc = 0.f, uacc = 0.f;
    // 512 float4 per row, 32 lanes -> 16 iterations
#pragma unroll
    for (int j = 0; j < 16; j++) {
        const int idx = j * 32 + lane;
        const float4 xv = x_s[idx];
        const float4 gv = g4[idx];
        const float4 uv = u4[idx];
        gacc += gv.x * xv.x + gv.y * xv.y + gv.z * xv.z + gv.w * xv.w;
        uacc += uv.x * xv.x + uv.y * xv.y + uv.z * xv.z + uv.w * xv.w;
    }

    // warp reduce
#pragma unroll
    for (int off = 16; off > 0; off >>= 1) {
        gacc += __shfl_xor_sync(0xFFFFFFFFu, gacc, off);
        uacc += __shfl_xor_sync(0xFFFFFFFFu, uacc, off);
    }

    if (lane == 0) {
        const float w = topk_w[e];
        const float silu = gacc / (1.0f + __expf(-gacc));
        g_inter[e * INTER + row] = w * silu * uacc;
    }
}

// ---------------------------------------------------------------------------
// Kernel 2: out[h] = sum_e dot(down[ex_e][h][:], g_inter[e][:])
// One warp per output h, covering ALL 4 experts -> 44 independent LDG.128.
// g_inter staged into smem once per block.
// grid: HIDDEN/4 = 512 blocks, block: 128 threads (4 warps, 1 h per warp)
// ---------------------------------------------------------------------------
__global__ __launch_bounds__(128)
void moe_down_kernel(const int*   __restrict__ topk_idx,
                     const float* __restrict__ down_all,
                     float*       __restrict__ out)
{
    __shared__ float4 i_s[TOP_K * INTER / 4];   // 1408 float4 = 22.5 KB

    const int tid  = threadIdx.x;
    const int lane = tid & 31;
    const int warp = tid >> 5;

    // Stage g_inter: 1408 float4 / 128 threads = 11 each
    const float4* gi4 = reinterpret_cast<const float4*>(g_inter);
#pragma unroll
    for (int k = 0; k < 11; k++)
        i_s[tid + k * 128] = gi4[tid + k * 128];
    __syncthreads();

    const int h = blockIdx.x * 4 + warp;        // 0..2047

    const long long e0 = topk_idx[0];
    const long long e1 = topk_idx[1];
    const long long e2 = topk_idx[2];
    const long long e3 = topk_idx[3];

    const float4* d0 = reinterpret_cast<const float4*>(down_all + (e0 * HIDDEN + h) * (long long)INTER);
    const float4* d1 = reinterpret_cast<const float4*>(down_all + (e1 * HIDDEN + h) * (long long)INTER);
    const float4* d2 = reinterpret_cast<const float4*>(down_all + (e2 * HIDDEN + h) * (long long)INTER);
    const float4* d3 = reinterpret_cast<const float4*>(down_all + (e3 * HIDDEN + h) * (long long)INTER);

    float acc0 = 0.f, acc1 = 0.f, acc2 = 0.f, acc3 = 0.f;
    // 352 float4 per expert row, 32 lanes -> 11 iterations, 4 experts interleaved
#pragma unroll
    for (int j = 0; j < 11; j++) {
        const int idx = j * 32 + lane;
        const float4 a0 = d0[idx];
        const float4 a1 = d1[idx];
        const float4 a2 = d2[idx];
        const float4 a3 = d3[idx];
        const float4 v0 = i_s[idx];
        const float4 v1 = i_s[idx + 352];
        const float4 v2 = i_s[idx + 704];
        const float4 v3 = i_s[idx + 1056];
        acc0 += a0.x * v0.x + a0.y * v0.y + a0.z * v0.z + a0.w * v0.w;
        acc1 += a1.x * v1.x + a1.y * v1.y + a1.z * v1.z + a1.w * v1.w;
        acc2 += a2.x * v2.x + a2.y * v2.y + a2.z * v2.z + a2.w * v2.w;
        acc3 += a3.x * v3.x + a3.y * v3.y + a3.z * v3.z + a3.w * v3.w;
    }

    float acc = (acc0 + acc1) + (acc2 + acc3);
#pragma unroll
    for (int off = 16; off > 0; off >>= 1)
        acc += __shfl_xor_sync(0xFFFFFFFFu, acc, off);

    if (lane == 0)
        out[h] = acc;
}

extern "C" void kernel_launch(void* const* d_in, const int* in_sizes, int n_in,
                              void* d_out, int out_size)
{
    const float* x        = (const float*)d_in[0];   // (1, 2048, 1, 1)
    const int*   topk_idx = (const int*)  d_in[1];   // (4,)
    const float* topk_w   = (const float*)d_in[2];   // (4,)
    const float* gate_all = (const float*)d_in[3];   // (60, 1408, 2048)
    const float* up_all   = (const float*)d_in[4];   // (60, 1408, 2048)
    const float* down_all = (const float*)d_in[5];   // (60, 2048, 1408)
    float* out = (float*)d_out;                      // (1, 2048, 1, 1)

    dim3 grid1(INTER / 8, TOP_K);
    moe_gate_up_kernel<<<grid1, 256>>>(x, topk_idx, topk_w, gate_all, up_all);
    moe_down_kernel<<<HIDDEN / 4, 128>>>(topk_idx, down_all, out);
}

// round 3
// speedup vs baseline: 1.0654x; 1.0654x over previous
#include <cuda_runtime.h>
#include <cuda_bf16.h>

#define HIDDEN 2048
#define INTER  1408
#define TOP_K  4

// Scratch for weighted intermediate activations: topk_w[e] * silu(gate)*up
__device__ float g_inter[TOP_K * INTER];

// ---------------------------------------------------------------------------
// Kernel 0: prefetch the 4 selected experts' down-projection blocks into L2.
// 4 experts x 11.5 MB = 46 MB = 360448 x 128B lines. Fire-and-forget; the
// fetches complete in the background while the gate/up kernel runs.
// grid: (88, 4), block 256: 88*256*4 = 90112 lines per expert (exact).
// ---------------------------------------------------------------------------
__global__ __launch_bounds__(256)
void prefetch_down_kernel(const int*   __restrict__ topk_idx,
                          const float* __restrict__ down_all)
{
    const long long ex = topk_idx[blockIdx.y];
    const char* base = reinterpret_cast<const char*>(
        down_all + ex * (long long)(HIDDEN * INTER));
    const long long line0 = ((long long)blockIdx.x * 256 + threadIdx.x) * 4;
#pragma unroll
    for (int i = 0; i < 4; i++) {
        asm volatile("prefetch.global.L2 [%0];"
                     :: "l"(base + (line0 + i) * 128));
    }
}

// ---------------------------------------------------------------------------
// Kernel 1: for each selected expert e and each intermediate row i:
//   g = dot(gate[ex][i][:], x);  u = dot(up[ex][i][:], x);
//   g_inter[e][i] = topk_w[e] * silu(g) * u
// Weight loads use __ldcs (evict-first) so this 92 MB stream does not evict
// the prefetched down-matrix data from L2.
// grid: (176, 4), block: 256 threads (8 warps, 1 row per warp)
// ---------------------------------------------------------------------------
__global__ __launch_bounds__(256)
void moe_gate_up_kernel(const float* __restrict__ x,
                        const int*   __restrict__ topk_idx,
                        const float* __restrict__ topk_w,
                        const float* __restrict__ gate_all,
                        const float* __restrict__ up_all)
{
    __shared__ float4 x_s[HIDDEN / 4];   // 8 KB

    const int tid  = threadIdx.x;
    const int lane = tid & 31;
    const int warp = tid >> 5;

    // Stage x into shared memory: 512 float4 / 256 threads = 2 each
    const float4* x4 = reinterpret_cast<const float4*>(x);
    x_s[tid]       = x4[tid];
    x_s[tid + 256] = x4[tid + 256];
    __syncthreads();

    const int e   = blockIdx.y;                 // expert slot 0..3
    const int row = blockIdx.x * 8 + warp;      // 0..1407
    const long long ex = topk_idx[e];

    const float4* g4 = reinterpret_cast<const float4*>(
        gate_all + (ex * INTER + row) * (long long)HIDDEN);
    const float4* u4 = reinterpret_cast<const float4*>(
        up_all   + (ex * INTER + row) * (long long)HIDDEN);

    float gacc = 0.f, uacc = 0.f;
    // 512 float4 per row, 32 lanes -> 16 iterations
#pragma unroll
    for (int j = 0; j < 16; j++) {
        const int idx = j * 32 + lane;
        const float4 xv = x_s[idx];
        const float4 gv = __ldcs(g4 + idx);   // streaming: evict-first
        const float4 uv = __ldcs(u4 + idx);
        gacc += gv.x * xv.x + gv.y * xv.y + gv.z * xv.z + gv.w * xv.w;
        uacc += uv.x * xv.x + uv.y * xv.y + uv.z * xv.z + uv.w * xv.w;
    }

    // warp reduce
#pragma unroll
    for (int off = 16; off > 0; off >>= 1) {
        gacc += __shfl_xor_sync(0xFFFFFFFFu, gacc, off);
        uacc += __shfl_xor_sync(0xFFFFFFFFu, uacc, off);
    }

    if (lane == 0) {
        const float w = topk_w[e];
        const float silu = gacc / (1.0f + __expf(-gacc));
        g_inter[e * INTER + row] = w * silu * uacc;
    }
}

// ---------------------------------------------------------------------------
// Kernel 2: out[h] = sum_e dot(down[ex_e][h][:], g_inter[e][:])
// Warp per h over an expert PAIR (grid.y selects the pair): 22 independent
// LDG.128 per warp, gi pair staged in smem (conflict-free LDS.128).
// Pairs combined via atomicAdd (2 commutative float adds per h ->
// deterministic). out is zeroed by cudaMemsetAsync before launch.
// grid: (256, 2), block: 256 threads (8 warps, 1 h per warp)
// ---------------------------------------------------------------------------
__global__ __launch_bounds__(256)
void moe_down_kernel(const int*   __restrict__ topk_idx,
                     const float* __restrict__ down_all,
                     float*       __restrict__ out)
{
    __shared__ float4 gi_s[2 * INTER / 4];   // 704 float4 = 11.25 KB

    const int tid  = threadIdx.x;
    const int lane = tid & 31;
    const int warp = tid >> 5;
    const int p    = blockIdx.y;             // expert pair 0..1

    // Stage g_inter for experts 2p, 2p+1
    const float4* gi4 = reinterpret_cast<const float4*>(g_inter + 2 * p * INTER);
    for (int k = tid; k < 704; k += 256)
        gi_s[k] = gi4[k];
    __syncthreads();

    const int h = blockIdx.x * 8 + warp;     // 0..2047

    const long long e0 = topk_idx[2 * p];
    const long long e1 = topk_idx[2 * p + 1];
    const float4* d0 = reinterpret_cast<const float4*>(
        down_all + (e0 * HIDDEN + h) * (long long)INTER);
    const float4* d1 = reinterpret_cast<const float4*>(
        down_all + (e1 * HIDDEN + h) * (long long)INTER);

    float acc0 = 0.f, acc1 = 0.f;
    // 352 float4 per expert row, 32 lanes -> 11 iterations, 2 experts
#pragma unroll
    for (int j = 0; j < 11; j++) {
        const int idx = j * 32 + lane;
        const float4 a0 = d0[idx];
        const float4 a1 = d1[idx];
        const float4 v0 = gi_s[idx];
        const float4 v1 = gi_s[idx + 352];
        acc0 += a0.x * v0.x + a0.y * v0.y + a0.z * v0.z + a0.w * v0.w;
        acc1 += a1.x * v1.x + a1.y * v1.y + a1.z * v1.z + a1.w * v1.w;
    }

    float acc = acc0 + acc1;
#pragma unroll
    for (int off = 16; off > 0; off >>= 1)
        acc += __shfl_xor_sync(0xFFFFFFFFu, acc, off);

    if (lane == 0)
        atomicAdd(&out[h], acc);
}

extern "C" void kernel_launch(void* const* d_in, const int* in_sizes, int n_in,
                              void* d_out, int out_size)
{
    const float* x        = (const float*)d_in[0];   // (1, 2048, 1, 1)
    const int*   topk_idx = (const int*)  d_in[1];   // (4,)
    const float* topk_w   = (const float*)d_in[2];   // (4,)
    const float* gate_all = (const float*)d_in[3];   // (60, 1408, 2048)
    const float* up_all   = (const float*)d_in[4];   // (60, 1408, 2048)
    const float* down_all = (const float*)d_in[5];   // (60, 2048, 1408)
    float* out = (float*)d_out;                      // (1, 2048, 1, 1)

    cudaMemsetAsync(out, 0, HIDDEN * sizeof(float));

    prefetch_down_kernel<<<dim3(88, 4), 256>>>(topk_idx, down_all);

    dim3 grid1(INTER / 8, TOP_K);
    moe_gate_up_kernel<<<grid1, 256>>>(x, topk_idx, topk_w, gate_all, up_all);

    moe_down_kernel<<<dim3(HIDDEN / 8, 2), 256>>>(topk_idx, down_all, out);
}